// round 8
// baseline (speedup 1.0000x reference)
#include <cuda_runtime.h>

// Problem constants (fixed by reference: B=8, H=512, W=512)
#define HH 512
#define WW 512
constexpr int HW    = HH * WW;       // 262144
constexpr int NPIX  = 8 * HW;        // 2097152
constexpr int NVEC  = NPIX / 4;      // 524288
constexpr int TPB   = 256;
constexpr int GRID  = NVEC / 2 / TPB; // 1024 (each thread: 2 quanta)
constexpr int VHALF = NVEC / 2;       // 262144

__device__ double       g_accum = 0.0;
__device__ unsigned int g_done  = 0;

__device__ __forceinline__ float4 ld4(const float* p) {
    return __ldg(reinterpret_cast<const float4*>(p));
}
__device__ __forceinline__ float clipf(float v) {
    return fminf(fmaxf(v, 1e-10f), 1.0f);
}

struct Quantum {
    int p, x4, y, c0;
    bool edgeL, edgeR;
    float4 r4, h04, h14, h24;
};

__device__ __forceinline__ void init_q(Quantum& q, int v,
    const float* __restrict__ roi, const float* __restrict__ hm0,
    const float* __restrict__ hm1, const float* __restrict__ hm2)
{
    q.p  = v << 2;
    q.x4 = q.p & (WW - 1);
    q.y  = (q.p >> 9) & (HH - 1);
    const int bb = q.p >> 18;
    q.c0 = bb * (9 * HW) + q.y * WW + q.x4;
    q.edgeL = (q.x4 == 0);
    q.edgeR = (q.x4 == WW - 4);
    q.r4  = ld4(roi + q.p);
    q.h04 = ld4(hm0 + q.p);
    q.h14 = ld4(hm1 + q.p);
    q.h24 = ld4(hm2 + q.p);
}

// rec pair contribution: sum_j w[j]*scale*((u-h)^2 + (w-h)^2)
__device__ __forceinline__ float rec_pair(const float4& uv, const float4& wv,
                                          const float4& hv, const float* wgt,
                                          float scale)
{
    const float* U = (const float*)&uv;
    const float* W = (const float*)&wv;
    const float* H = (const float*)&hv;
    float s = 0.0f;
    #pragma unroll
    for (int j = 0; j < 4; j++) {
        const float d0 = U[j] - H[j], d1 = W[j] - H[j];
        s += wgt[j] * scale * (d0 * d0 + d1 * d1);
    }
    return s;
}

__global__ void __launch_bounds__(TPB) flow_loss_k(
    const float* __restrict__ roi,
    const float* __restrict__ hm0,  const float* __restrict__ hm1,  const float* __restrict__ hm2,
    const float* __restrict__ r1pf, const float* __restrict__ r1pb,
    const float* __restrict__ r1nf, const float* __restrict__ r1nb,
    const float* __restrict__ r0f,  const float* __restrict__ r0b,
    const float* __restrict__ r2f,  const float* __restrict__ r2b,
    const float* __restrict__ fA1,  const float* __restrict__ fB1,   // flow_0_1f, flow_1_0b
    const float* __restrict__ fA2,  const float* __restrict__ fB2,   // flow_1_2f, flow_2_1b
    float* __restrict__ out)
{
    const int v0 = blockIdx.x * TPB + threadIdx.x;
    const int v1 = v0 + VHALF;

    Quantum qa, qb;
    init_q(qa, v0, roi, hm0, hm1, hm2);
    init_q(qb, v1, roi, hm0, hm1, hm2);

    float wpa[4], wna[4], wpb[4], wnb[4];
    {
        const float* R  = (const float*)&qa.r4;
        const float* H0 = (const float*)&qa.h04;
        const float* H1 = (const float*)&qa.h14;
        const float* H2 = (const float*)&qa.h24;
        #pragma unroll
        for (int j = 0; j < 4; j++) {
            wpa[j] = R[j] * (1.0f + fabsf(H0[j] - H1[j]));
            wna[j] = R[j] * (1.0f + fabsf(H1[j] - H2[j]));
        }
    }
    {
        const float* R  = (const float*)&qb.r4;
        const float* H0 = (const float*)&qb.h04;
        const float* H1 = (const float*)&qb.h14;
        const float* H2 = (const float*)&qb.h24;
        #pragma unroll
        for (int j = 0; j < 4; j++) {
            wpb[j] = R[j] * (1.0f + fabsf(H0[j] - H1[j]));
            wnb[j] = R[j] * (1.0f + fabsf(H1[j] - H2[j]));
        }
    }

    float acc = 0.0f;

    // ---- rec streams: pairs for both quanta loaded together (4 independent LDG.128) ----
    {
        const float4 ua = ld4(r1pf + qa.p), wa = ld4(r1pb + qa.p);
        const float4 ub = ld4(r1pf + qb.p), wb = ld4(r1pb + qb.p);
        acc += rec_pair(ua, wa, qa.h14, wpa, 0.25f);
        acc += rec_pair(ub, wb, qb.h14, wpb, 0.25f);
    }
    {
        const float4 ua = ld4(r1nf + qa.p), wa = ld4(r1nb + qa.p);
        const float4 ub = ld4(r1nf + qb.p), wb = ld4(r1nb + qb.p);
        acc += rec_pair(ua, wa, qa.h14, wna, 0.25f);
        acc += rec_pair(ub, wb, qb.h14, wnb, 0.25f);
    }
    {
        const float4 ua = ld4(r0f + qa.p), wa = ld4(r0b + qa.p);
        const float4 ub = ld4(r0f + qb.p), wb = ld4(r0b + qb.p);
        acc += rec_pair(ua, wa, qa.h04, wpa, 0.5f);
        acc += rec_pair(ub, wb, qb.h04, wpb, 0.5f);
    }
    {
        const float4 ua = ld4(r2f + qa.p), wa = ld4(r2b + qa.p);
        const float4 ub = ld4(r2f + qb.p), wb = ld4(r2b + qb.p);
        acc += rec_pair(ua, wa, qa.h24, wna, 0.5f);
        acc += rec_pair(ub, wb, qb.h24, wnb, 0.5f);
    }

    // ---- flow consistency: both quanta per channel iteration (8 independent LDG.128/iter) ----
    float fa[4] = {0.f,0.f,0.f,0.f};
    float fb[4] = {0.f,0.f,0.f,0.f};

    #pragma unroll
    for (int i = 0; i < 9; i++) {
        const int dy = (i < 3) ? 1 : ((i < 6) ? 0 : -1);
        const int m  = i % 3;
        const int dx = (m == 0) ? 1 : ((m == 1) ? 0 : -1);

        #pragma unroll
        for (int qi = 0; qi < 2; qi++) {
            const Quantum& q = qi ? qb : qa;
            float* facc = qi ? fb : fa;

            const bool vrow = (dy == 1) ? (q.y >= 1) : ((dy == -1) ? (q.y <= HH - 2) : true);
            if (!vrow) continue;

            const int ao = q.c0 + i * HW;
            const int go = q.c0 + (8 - i) * HW - dy * WW;

            const float4 av1 = ld4(fA1 + ao);
            const float4 av2 = ld4(fA2 + ao);
            const float4 bv1 = ld4(fB1 + go);
            const float4 bv2 = ld4(fB2 + go);
            const float* A1  = (const float*)&av1; const float* A2  = (const float*)&av2;
            const float* B1  = (const float*)&bv1; const float* B2  = (const float*)&bv2;

            if (dx == 0) {
                #pragma unroll
                for (int j = 0; j < 4; j++) {
                    const float d1 = clipf(A1[j]) - clipf(B1[j]);
                    const float d2 = clipf(A2[j]) - clipf(B2[j]);
                    facc[j] += d1 * d1 + d2 * d2;
                }
            } else if (dx == 1) {
                if (!q.edgeL) {
                    const float d1 = clipf(A1[0]) - clipf(__ldg(fB1 + go - 1));
                    const float d2 = clipf(A2[0]) - clipf(__ldg(fB2 + go - 1));
                    facc[0] += d1 * d1 + d2 * d2;
                }
                #pragma unroll
                for (int j = 1; j < 4; j++) {
                    const float d1 = clipf(A1[j]) - clipf(B1[j - 1]);
                    const float d2 = clipf(A2[j]) - clipf(B2[j - 1]);
                    facc[j] += d1 * d1 + d2 * d2;
                }
            } else {  // dx == -1
                #pragma unroll
                for (int j = 0; j < 3; j++) {
                    const float d1 = clipf(A1[j]) - clipf(B1[j + 1]);
                    const float d2 = clipf(A2[j]) - clipf(B2[j + 1]);
                    facc[j] += d1 * d1 + d2 * d2;
                }
                if (!q.edgeR) {
                    const float d1 = clipf(A1[3]) - clipf(__ldg(fB1 + go + 4));
                    const float d2 = clipf(A2[3]) - clipf(__ldg(fB2 + go + 4));
                    facc[3] += d1 * d1 + d2 * d2;
                }
            }
        }
    }

    {
        const float* Ra = (const float*)&qa.r4;
        const float* Rb = (const float*)&qb.r4;
        #pragma unroll
        for (int j = 0; j < 4; j++)
            acc += (fa[j] * Ra[j] + fb[j] * Rb[j]) * (1.0f / 9.0f);
    }

    // ---- block reduction: warp shuffle -> shared -> warp 0 -> atomicAdd(double) ----
    __shared__ float sdata[TPB / 32];
    #pragma unroll
    for (int off = 16; off; off >>= 1)
        acc += __shfl_down_sync(0xffffffffu, acc, off);
    const int lane = threadIdx.x & 31;
    const int wid  = threadIdx.x >> 5;
    if (lane == 0) sdata[wid] = acc;
    __syncthreads();

    if (wid == 0) {
        float t = (lane < TPB / 32) ? sdata[lane] : 0.0f;
        #pragma unroll
        for (int off = 4; off; off >>= 1)
            t += __shfl_down_sync(0xffffffffu, t, off);

        if (lane == 0) {
            atomicAdd(&g_accum, (double)t);
            __threadfence();
            const unsigned int ticket = atomicAdd(&g_done, 1u);
            if (ticket == gridDim.x - 1) {
                out[0] = (float)g_accum;
                g_accum = 0.0;          // reset for next graph replay
                __threadfence();
                g_done = 0;
            }
        }
    }
}

extern "C" void kernel_launch(void* const* d_in, const int* in_sizes, int n_in,
                              void* d_out, int out_size) {
    const float* roi  = (const float*)d_in[0];
    // d_in[1] = boundary_mask : unused by the reference loss
    const float* hm0  = (const float*)d_in[2];
    const float* hm1  = (const float*)d_in[3];
    const float* hm2  = (const float*)d_in[4];
    const float* r1pf = (const float*)d_in[5];
    const float* r1pb = (const float*)d_in[6];
    const float* r1nf = (const float*)d_in[7];
    const float* r1nb = (const float*)d_in[8];
    const float* r0f  = (const float*)d_in[9];
    const float* r0b  = (const float*)d_in[10];
    const float* r2f  = (const float*)d_in[11];
    const float* r2b  = (const float*)d_in[12];
    const float* fA1  = (const float*)d_in[13];
    const float* fB1  = (const float*)d_in[14];
    const float* fA2  = (const float*)d_in[15];
    const float* fB2  = (const float*)d_in[16];

    flow_loss_k<<<GRID, TPB>>>(roi, hm0, hm1, hm2,
                               r1pf, r1pb, r1nf, r1nb,
                               r0f, r0b, r2f, r2b,
                               fA1, fB1, fA2, fB2,
                               (float*)d_out);
}

// round 9
// speedup vs baseline: 1.1401x; 1.1401x over previous
#include <cuda_runtime.h>

// Problem constants (fixed by reference: B=8, H=512, W=512)
#define HH 512
#define WW 512
constexpr int HW   = HH * WW;        // 262144
constexpr int NPIX = 8 * HW;         // 2097152
constexpr int NVEC = NPIX / 4;       // 524288 float4-quanta
constexpr int TPB  = 384;            // 36 warps/SM at 3 CTAs (regs capped at 56)
constexpr int GRID = (NVEC + TPB - 1) / TPB;  // 1366

__device__ double       g_accum = 0.0;
__device__ unsigned int g_done  = 0;

__device__ __forceinline__ float4 ld4(const float* p) {
    return __ldg(reinterpret_cast<const float4*>(p));
}
__device__ __forceinline__ float clipf(float v) {
    return fminf(fmaxf(v, 1e-10f), 1.0f);
}

__global__ void __launch_bounds__(TPB, 3) flow_loss_k(
    const float* __restrict__ roi,
    const float* __restrict__ hm0,  const float* __restrict__ hm1,  const float* __restrict__ hm2,
    const float* __restrict__ r1pf, const float* __restrict__ r1pb,
    const float* __restrict__ r1nf, const float* __restrict__ r1nb,
    const float* __restrict__ r0f,  const float* __restrict__ r0b,
    const float* __restrict__ r2f,  const float* __restrict__ r2b,
    const float* __restrict__ fA1,  const float* __restrict__ fB1,   // flow_0_1f, flow_1_0b
    const float* __restrict__ fA2,  const float* __restrict__ fB2,   // flow_1_2f, flow_2_1b
    float* __restrict__ out)
{
    const int v = blockIdx.x * TPB + threadIdx.x;   // vector id (4 pixels)
    float acc = 0.0f;

    if (v < NVEC) {
        const int p  = v << 2;
        const int x4 = p & (WW - 1);            // 0,4,...,508
        const int y  = (p >> 9) & (HH - 1);
        const int bb = p >> 18;

        // ---- aligned streams: 12 x LDG.128 (front-batched) ----
        const float4 r4  = ld4(roi  + p);
        const float4 h04 = ld4(hm0  + p);
        const float4 h14 = ld4(hm1  + p);
        const float4 h24 = ld4(hm2  + p);
        const float4 a1p = ld4(r1pf + p);
        const float4 b1p = ld4(r1pb + p);
        const float4 a1n = ld4(r1nf + p);
        const float4 b1n = ld4(r1nb + p);
        const float4 a0  = ld4(r0f  + p);
        const float4 b0  = ld4(r0b  + p);
        const float4 a2  = ld4(r2f  + p);
        const float4 b2  = ld4(r2b  + p);

        const float* R   = (const float*)&r4;
        const float* H0  = (const float*)&h04;
        const float* H1  = (const float*)&h14;
        const float* H2  = (const float*)&h24;
        const float* P1F = (const float*)&a1p; const float* P1B = (const float*)&b1p;
        const float* N1F = (const float*)&a1n; const float* N1B = (const float*)&b1n;
        const float* F0  = (const float*)&a0;  const float* B0  = (const float*)&b0;
        const float* F2  = (const float*)&a2;  const float* B2  = (const float*)&b2;

        #pragma unroll
        for (int j = 0; j < 4; j++) {
            const float r  = R[j];
            const float h0 = H0[j], h1 = H1[j], h2 = H2[j];
            const float pre  = fabsf(h0 - h1);
            const float post = fabsf(h1 - h2);

            float d;
            d = P1F[j] - h1; float s1p = d * d;
            d = P1B[j] - h1; s1p += d * d;
            d = N1F[j] - h1; float s1n = d * d;
            d = N1B[j] - h1; s1n += d * d;
            d = F0[j]  - h0; float s0  = d * d;
            d = B0[j]  - h0; s0  += d * d;
            d = F2[j]  - h2; float s2  = d * d;
            d = B2[j]  - h2; s2  += d * d;

            acc += r * (1.0f + pre)  * (0.25f * s1p + 0.5f * s0)
                 + r * (1.0f + post) * (0.25f * s1n + 0.5f * s2);
        }

        // ---- flow consistency (both pairs share index math) ----
        float facc[4] = {0.f, 0.f, 0.f, 0.f};
        const int c0 = bb * (9 * HW) + y * WW + x4;   // channel 0 at (y, x4)
        const bool edgeL = (x4 == 0);                 // lane 0 invalid for dx=+1
        const bool edgeR = (x4 == WW - 4);            // lane 3 invalid for dx=-1

        #pragma unroll
        for (int i = 0; i < 9; i++) {
            const int dy = (i < 3) ? 1 : ((i < 6) ? 0 : -1);
            const int m  = i % 3;
            const int dx = (m == 0) ? 1 : ((m == 1) ? 0 : -1);

            const bool vrow = (dy == 1) ? (y >= 1) : ((dy == -1) ? (y <= HH - 2) : true);
            if (!vrow) continue;

            const int ao = c0 + i * HW;
            const int go = c0 + (8 - i) * HW - dy * WW;   // aligned base (dx via lane shift)

            const float4 av1 = ld4(fA1 + ao);
            const float4 av2 = ld4(fA2 + ao);
            const float4 bv1 = ld4(fB1 + go);
            const float4 bv2 = ld4(fB2 + go);
            const float* A1  = (const float*)&av1; const float* A2  = (const float*)&av2;
            const float* Bv1 = (const float*)&bv1; const float* Bv2 = (const float*)&bv2;

            if (dx == 0) {
                #pragma unroll
                for (int j = 0; j < 4; j++) {
                    const float d1 = clipf(A1[j]) - clipf(Bv1[j]);
                    const float d2 = clipf(A2[j]) - clipf(Bv2[j]);
                    facc[j] += d1 * d1 + d2 * d2;
                }
            } else if (dx == 1) {
                // lane j needs b at x4+j-1; lane 0 straddles (scalar), invalid at x4==0
                if (!edgeL) {
                    const float d1 = clipf(A1[0]) - clipf(__ldg(fB1 + go - 1));
                    const float d2 = clipf(A2[0]) - clipf(__ldg(fB2 + go - 1));
                    facc[0] += d1 * d1 + d2 * d2;
                }
                #pragma unroll
                for (int j = 1; j < 4; j++) {
                    const float d1 = clipf(A1[j]) - clipf(Bv1[j - 1]);
                    const float d2 = clipf(A2[j]) - clipf(Bv2[j - 1]);
                    facc[j] += d1 * d1 + d2 * d2;
                }
            } else {  // dx == -1
                // lane j needs b at x4+j+1; lane 3 straddles (scalar), invalid at x4==508
                #pragma unroll
                for (int j = 0; j < 3; j++) {
                    const float d1 = clipf(A1[j]) - clipf(Bv1[j + 1]);
                    const float d2 = clipf(A2[j]) - clipf(Bv2[j + 1]);
                    facc[j] += d1 * d1 + d2 * d2;
                }
                if (!edgeR) {
                    const float d1 = clipf(A1[3]) - clipf(__ldg(fB1 + go + 4));
                    const float d2 = clipf(A2[3]) - clipf(__ldg(fB2 + go + 4));
                    facc[3] += d1 * d1 + d2 * d2;
                }
            }
        }
        #pragma unroll
        for (int j = 0; j < 4; j++) acc += facc[j] * R[j] * (1.0f / 9.0f);
    }

    // ---- block reduction: warp shuffle -> shared -> warp 0 -> atomicAdd(double) ----
    __shared__ float sdata[TPB / 32];
    #pragma unroll
    for (int off = 16; off; off >>= 1)
        acc += __shfl_down_sync(0xffffffffu, acc, off);
    const int lane = threadIdx.x & 31;
    const int wid  = threadIdx.x >> 5;
    if (lane == 0) sdata[wid] = acc;
    __syncthreads();

    if (wid == 0) {
        float t = (lane < TPB / 32) ? sdata[lane] : 0.0f;
        #pragma unroll
        for (int off = 8; off; off >>= 1)
            t += __shfl_down_sync(0xffffffffu, t, off);

        if (lane == 0) {
            atomicAdd(&g_accum, (double)t);
            __threadfence();
            const unsigned int ticket = atomicAdd(&g_done, 1u);
            if (ticket == gridDim.x - 1) {
                out[0] = (float)g_accum;
                g_accum = 0.0;          // reset for next graph replay
                __threadfence();
                g_done = 0;
            }
        }
    }
}

extern "C" void kernel_launch(void* const* d_in, const int* in_sizes, int n_in,
                              void* d_out, int out_size) {
    const float* roi  = (const float*)d_in[0];
    // d_in[1] = boundary_mask : unused by the reference loss
    const float* hm0  = (const float*)d_in[2];
    const float* hm1  = (const float*)d_in[3];
    const float* hm2  = (const float*)d_in[4];
    const float* r1pf = (const float*)d_in[5];
    const float* r1pb = (const float*)d_in[6];
    const float* r1nf = (const float*)d_in[7];
    const float* r1nb = (const float*)d_in[8];
    const float* r0f  = (const float*)d_in[9];
    const float* r0b  = (const float*)d_in[10];
    const float* r2f  = (const float*)d_in[11];
    const float* r2b  = (const float*)d_in[12];
    const float* fA1  = (const float*)d_in[13];
    const float* fB1  = (const float*)d_in[14];
    const float* fA2  = (const float*)d_in[15];
    const float* fB2  = (const float*)d_in[16];

    flow_loss_k<<<GRID, TPB>>>(roi, hm0, hm1, hm2,
                               r1pf, r1pb, r1nf, r1nb,
                               r0f, r0b, r2f, r2b,
                               fA1, fB1, fA2, fB2,
                               (float*)d_out);
}

// round 10
// speedup vs baseline: 1.2031x; 1.0553x over previous
#include <cuda_runtime.h>

// Problem constants (fixed by reference: B=8, H=512, W=512)
#define HH 512
#define WW 512
constexpr int HW   = HH * WW;        // 262144
constexpr int NPIX = 8 * HW;         // 2097152
constexpr int NVEC = NPIX / 4;       // 524288 float4-quanta
constexpr int TPB  = 384;            // 36 warps/SM at 3 CTAs (regs capped at 56)
constexpr int GRID = (NVEC + TPB - 1) / TPB;  // 1366

__device__ double       g_accum = 0.0;
__device__ unsigned int g_done  = 0;

// evict-first streaming load: data is read exactly once chip-wide
__device__ __forceinline__ float4 ld4_cs(const float* p) {
    return __ldcs(reinterpret_cast<const float4*>(p));
}
// default cached load: sectors shared with neighboring threads (straddle paths)
__device__ __forceinline__ float4 ld4(const float* p) {
    return __ldg(reinterpret_cast<const float4*>(p));
}
__device__ __forceinline__ float clipf(float v) {
    return fminf(fmaxf(v, 1e-10f), 1.0f);
}

__global__ void __launch_bounds__(TPB, 3) flow_loss_k(
    const float* __restrict__ roi,
    const float* __restrict__ hm0,  const float* __restrict__ hm1,  const float* __restrict__ hm2,
    const float* __restrict__ r1pf, const float* __restrict__ r1pb,
    const float* __restrict__ r1nf, const float* __restrict__ r1nb,
    const float* __restrict__ r0f,  const float* __restrict__ r0b,
    const float* __restrict__ r2f,  const float* __restrict__ r2b,
    const float* __restrict__ fA1,  const float* __restrict__ fB1,   // flow_0_1f, flow_1_0b
    const float* __restrict__ fA2,  const float* __restrict__ fB2,   // flow_1_2f, flow_2_1b
    float* __restrict__ out)
{
    const int v = blockIdx.x * TPB + threadIdx.x;   // vector id (4 pixels)
    float acc = 0.0f;

    if (v < NVEC) {
        const int p  = v << 2;
        const int x4 = p & (WW - 1);            // 0,4,...,508
        const int y  = (p >> 9) & (HH - 1);
        const int bb = p >> 18;

        // ---- aligned streams: 12 x LDG.128, read-once -> evict-first ----
        const float4 r4  = ld4_cs(roi  + p);
        const float4 h04 = ld4_cs(hm0  + p);
        const float4 h14 = ld4_cs(hm1  + p);
        const float4 h24 = ld4_cs(hm2  + p);
        const float4 a1p = ld4_cs(r1pf + p);
        const float4 b1p = ld4_cs(r1pb + p);
        const float4 a1n = ld4_cs(r1nf + p);
        const float4 b1n = ld4_cs(r1nb + p);
        const float4 a0  = ld4_cs(r0f  + p);
        const float4 b0  = ld4_cs(r0b  + p);
        const float4 a2  = ld4_cs(r2f  + p);
        const float4 b2  = ld4_cs(r2b  + p);

        const float* R   = (const float*)&r4;
        const float* H0  = (const float*)&h04;
        const float* H1  = (const float*)&h14;
        const float* H2  = (const float*)&h24;
        const float* P1F = (const float*)&a1p; const float* P1B = (const float*)&b1p;
        const float* N1F = (const float*)&a1n; const float* N1B = (const float*)&b1n;
        const float* F0  = (const float*)&a0;  const float* B0  = (const float*)&b0;
        const float* F2  = (const float*)&a2;  const float* B2  = (const float*)&b2;

        #pragma unroll
        for (int j = 0; j < 4; j++) {
            const float r  = R[j];
            const float h0 = H0[j], h1 = H1[j], h2 = H2[j];
            const float pre  = fabsf(h0 - h1);
            const float post = fabsf(h1 - h2);

            float d;
            d = P1F[j] - h1; float s1p = d * d;
            d = P1B[j] - h1; s1p += d * d;
            d = N1F[j] - h1; float s1n = d * d;
            d = N1B[j] - h1; s1n += d * d;
            d = F0[j]  - h0; float s0  = d * d;
            d = B0[j]  - h0; s0  += d * d;
            d = F2[j]  - h2; float s2  = d * d;
            d = B2[j]  - h2; s2  += d * d;

            acc += r * (1.0f + pre)  * (0.25f * s1p + 0.5f * s0)
                 + r * (1.0f + post) * (0.25f * s1n + 0.5f * s2);
        }

        // ---- flow consistency (both pairs share index math) ----
        float facc[4] = {0.f, 0.f, 0.f, 0.f};
        const int c0 = bb * (9 * HW) + y * WW + x4;   // channel 0 at (y, x4)
        const bool edgeL = (x4 == 0);                 // lane 0 invalid for dx=+1
        const bool edgeR = (x4 == WW - 4);            // lane 3 invalid for dx=-1

        #pragma unroll
        for (int i = 0; i < 9; i++) {
            const int dy = (i < 3) ? 1 : ((i < 6) ? 0 : -1);
            const int m  = i % 3;
            const int dx = (m == 0) ? 1 : ((m == 1) ? 0 : -1);

            const bool vrow = (dy == 1) ? (y >= 1) : ((dy == -1) ? (y <= HH - 2) : true);
            if (!vrow) continue;

            const int ao = c0 + i * HW;
            const int go = c0 + (8 - i) * HW - dy * WW;   // aligned base (dx via lane shift)

            // fA: strictly read-once -> streaming
            const float4 av1 = ld4_cs(fA1 + ao);
            const float4 av2 = ld4_cs(fA2 + ao);
            const float* A1  = (const float*)&av1; const float* A2  = (const float*)&av2;

            if (dx == 0) {
                const float4 bv1 = ld4_cs(fB1 + go);
                const float4 bv2 = ld4_cs(fB2 + go);
                const float* Bv1 = (const float*)&bv1; const float* Bv2 = (const float*)&bv2;
                #pragma unroll
                for (int j = 0; j < 4; j++) {
                    const float d1 = clipf(A1[j]) - clipf(Bv1[j]);
                    const float d2 = clipf(A2[j]) - clipf(Bv2[j]);
                    facc[j] += d1 * d1 + d2 * d2;
                }
            } else if (dx == 1) {
                // straddle path: sectors shared with neighbor thread -> cached
                const float4 bv1 = ld4(fB1 + go);
                const float4 bv2 = ld4(fB2 + go);
                const float* Bv1 = (const float*)&bv1; const float* Bv2 = (const float*)&bv2;
                if (!edgeL) {
                    const float d1 = clipf(A1[0]) - clipf(__ldg(fB1 + go - 1));
                    const float d2 = clipf(A2[0]) - clipf(__ldg(fB2 + go - 1));
                    facc[0] += d1 * d1 + d2 * d2;
                }
                #pragma unroll
                for (int j = 1; j < 4; j++) {
                    const float d1 = clipf(A1[j]) - clipf(Bv1[j - 1]);
                    const float d2 = clipf(A2[j]) - clipf(Bv2[j - 1]);
                    facc[j] += d1 * d1 + d2 * d2;
                }
            } else {  // dx == -1
                const float4 bv1 = ld4(fB1 + go);
                const float4 bv2 = ld4(fB2 + go);
                const float* Bv1 = (const float*)&bv1; const float* Bv2 = (const float*)&bv2;
                #pragma unroll
                for (int j = 0; j < 3; j++) {
                    const float d1 = clipf(A1[j]) - clipf(Bv1[j + 1]);
                    const float d2 = clipf(A2[j]) - clipf(Bv2[j + 1]);
                    facc[j] += d1 * d1 + d2 * d2;
                }
                if (!edgeR) {
                    const float d1 = clipf(A1[3]) - clipf(__ldg(fB1 + go + 4));
                    const float d2 = clipf(A2[3]) - clipf(__ldg(fB2 + go + 4));
                    facc[3] += d1 * d1 + d2 * d2;
                }
            }
        }
        #pragma unroll
        for (int j = 0; j < 4; j++) acc += facc[j] * R[j] * (1.0f / 9.0f);
    }

    // ---- block reduction: warp shuffle -> shared -> warp 0 -> atomicAdd(double) ----
    __shared__ float sdata[TPB / 32];
    #pragma unroll
    for (int off = 16; off; off >>= 1)
        acc += __shfl_down_sync(0xffffffffu, acc, off);
    const int lane = threadIdx.x & 31;
    const int wid  = threadIdx.x >> 5;
    if (lane == 0) sdata[wid] = acc;
    __syncthreads();

    if (wid == 0) {
        float t = (lane < TPB / 32) ? sdata[lane] : 0.0f;
        #pragma unroll
        for (int off = 8; off; off >>= 1)
            t += __shfl_down_sync(0xffffffffu, t, off);

        if (lane == 0) {
            atomicAdd(&g_accum, (double)t);
            __threadfence();
            const unsigned int ticket = atomicAdd(&g_done, 1u);
            if (ticket == gridDim.x - 1) {
                out[0] = (float)g_accum;
                g_accum = 0.0;          // reset for next graph replay
                __threadfence();
                g_done = 0;
            }
        }
    }
}

extern "C" void kernel_launch(void* const* d_in, const int* in_sizes, int n_in,
                              void* d_out, int out_size) {
    const float* roi  = (const float*)d_in[0];
    // d_in[1] = boundary_mask : unused by the reference loss
    const float* hm0  = (const float*)d_in[2];
    const float* hm1  = (const float*)d_in[3];
    const float* hm2  = (const float*)d_in[4];
    const float* r1pf = (const float*)d_in[5];
    const float* r1pb = (const float*)d_in[6];
    const float* r1nf = (const float*)d_in[7];
    const float* r1nb = (const float*)d_in[8];
    const float* r0f  = (const float*)d_in[9];
    const float* r0b  = (const float*)d_in[10];
    const float* r2f  = (const float*)d_in[11];
    const float* r2b  = (const float*)d_in[12];
    const float* fA1  = (const float*)d_in[13];
    const float* fB1  = (const float*)d_in[14];
    const float* fA2  = (const float*)d_in[15];
    const float* fB2  = (const float*)d_in[16];

    flow_loss_k<<<GRID, TPB>>>(roi, hm0, hm1, hm2,
                               r1pf, r1pb, r1nf, r1nb,
                               r0f, r0b, r2f, r2b,
                               fA1, fB1, fA2, fB2,
                               (float*)d_out);
}